// round 12
// baseline (speedup 1.0000x reference)
#include <cuda_runtime.h>

// DilateAttention: B=8, C=384 (12 heads x 32), H=W=56, kernel 3x3, dilation 2, pad 2.
// q,k,v: [B, C, H, W] f32. out: [B, H, W, C] f32.
//
// R12 = R7 (best measured load structure: 2 px/thread, float2 window loads,
// per-window guards, CC=8 chunks) + R5's store fix done at full strength:
// output staged in smem in two 16-channel groups and written cooperatively
// (4 lanes per pixel x float4 -> contiguous 64B segments, ~2 wf/px instead of
// ~8 wf/px of scattered STG.128, and far fewer store-issue slots stealing MIO
// bandwidth from the loads).

#define HD     32
#define HEADS  12
#define WD     56
#define HT     56
#define BD     8
#define HW     (WD * HT)
#define CTOT   384
#define XG     28          // x-pairs per row
#define NTHR   128
#define PXB    (NTHR * 2)  // 256 pixels per block
#define CC     8
#define NCH    (HD / CC)   // 4
#define SPITCH 20          // stage pitch in floats (16B-aligned, low-conflict)

__global__ __launch_bounds__(NTHR)
void dilate_attn_kernel(const float* __restrict__ q,
                        const float* __restrict__ k,
                        const float* __restrict__ v,
                        float* __restrict__ out)
{
    __shared__ __align__(16) float stage[PXB * SPITCH];  // 20 KB
    __shared__ int sOb[PXB];                             // 1 KB

    const int tid  = threadIdx.x;
    const int gid  = blockIdx.x * NTHR + tid;
    const int xg   = gid % XG;
    int r1         = gid / XG;
    const int y    = r1 % HT;
    int r2         = r1 / HT;
    const int head = r2 % HEADS;
    const int b    = r2 / HEADS;
    const int x0   = xg * 2;

    const int base = (b * CTOT + head * HD) * HW;
    const int pix  = y * WD + x0;

    {
        int ob = ((b * HT + y) * WD + x0) * CTOT + head * HD;
        sOb[2 * tid]     = ob;
        sOb[2 * tid + 1] = ob + CTOT;
    }

    const bool cL = (x0 >= 2);
    const bool cR = (x0 <= WD - 4);
    const bool yT = (y >= 2);
    const bool yB = (y <= HT - 3);

    const bool vmask[9] = {
        yT && cL, yT, yT && cR,
        cL,       true, cR,
        yB && cL, yB, yB && cR
    };
    const int voff[9] = {
        -2 * WD - 2, -2 * WD, -2 * WD + 2,
        -2,           0,       2,
         2 * WD - 2,  2 * WD,  2 * WD + 2
    };

    const float* qc = q + base + pix;
    const float* kc = k + base + pix;
    const float* vc = v + base + pix;

    const float scale = 0.17677669529663687f;  // 32^-0.5

    float a0[9], a1[9];
#pragma unroll
    for (int p = 0; p < 9; p++) { a0[p] = 0.0f; a1[p] = 0.0f; }

    // ================= K phase: logits, channel chunks of 8 =================
#pragma unroll
    for (int ch = 0; ch < NCH; ch++) {
        float2 qv[CC];
#pragma unroll
        for (int c = 0; c < CC; c++) {
            qv[c] = *(const float2*)(qc + (ch * CC + c) * HW);
            qv[c].x *= scale; qv[c].y *= scale;
        }

#pragma unroll
        for (int p = 0; p < 9; p++) {
            if (vmask[p]) {
                const float* kp = kc + ch * CC * HW + voff[p];
                float s0 = a0[p], s1 = a1[p];
#pragma unroll
                for (int c = 0; c < CC; c++) {
                    float2 kv = *(const float2*)(kp + c * HW);
                    s0 = fmaf(qv[c].x, kv.x, s0);
                    s1 = fmaf(qv[c].y, kv.y, s1);
                }
                a0[p] = s0; a1[p] = s1;
            }
        }
    }

    // ================= softmax (normalization folded into weights) =================
    {
        float m0 = -1e30f, m1 = -1e30f;
#pragma unroll
        for (int p = 0; p < 9; p++) { m0 = fmaxf(m0, a0[p]); m1 = fmaxf(m1, a1[p]); }
        float d0 = 0.0f, d1 = 0.0f;
#pragma unroll
        for (int p = 0; p < 9; p++) {
            a0[p] = __expf(a0[p] - m0); d0 += a0[p];
            a1[p] = __expf(a1[p] - m1); d1 += a1[p];
        }
        float i0 = 1.0f / d0, i1 = 1.0f / d1;
#pragma unroll
        for (int p = 0; p < 9; p++) { a0[p] *= i0; a1[p] *= i1; }
    }

    // ================= V phase: 2 groups of 2 chunks, staged stores =================
#pragma unroll
    for (int g = 0; g < 2; g++) {
#pragma unroll
        for (int chh = 0; chh < 2; chh++) {
            const int ch = g * 2 + chh;
            float acc0[CC], acc1[CC];
#pragma unroll
            for (int c = 0; c < CC; c++) { acc0[c] = 0.0f; acc1[c] = 0.0f; }

#pragma unroll
            for (int p = 0; p < 9; p++) {
                if (vmask[p]) {
                    const float w0 = a0[p], w1 = a1[p];
                    const float* vp = vc + ch * CC * HW + voff[p];
#pragma unroll
                    for (int c = 0; c < CC; c++) {
                        float2 vv = *(const float2*)(vp + c * HW);
                        acc0[c] = fmaf(w0, vv.x, acc0[c]);
                        acc1[c] = fmaf(w1, vv.y, acc1[c]);
                    }
                }
            }

            float* st0 = &stage[(2 * tid)     * SPITCH + chh * CC];
            float* st1 = &stage[(2 * tid + 1) * SPITCH + chh * CC];
            *(float4*)(st0)     = make_float4(acc0[0], acc0[1], acc0[2], acc0[3]);
            *(float4*)(st0 + 4) = make_float4(acc0[4], acc0[5], acc0[6], acc0[7]);
            *(float4*)(st1)     = make_float4(acc1[0], acc1[1], acc1[2], acc1[3]);
            *(float4*)(st1 + 4) = make_float4(acc1[4], acc1[5], acc1[6], acc1[7]);
        }
        __syncthreads();

        // cooperative store of this 16-channel group: 4 lanes/px, 64B contiguous per px
#pragma unroll
        for (int r = 0; r < 8; r++) {
            int idx = tid + NTHR * r;        // 0..1023
            int px  = idx >> 2;              // 0..255
            int ci  = (idx & 3) << 2;        // 0,4,8,12
            float4 val = *(const float4*)&stage[px * SPITCH + ci];
            *(float4*)(out + sOb[px] + g * 16 + ci) = val;
        }
        __syncthreads();
    }
}

extern "C" void kernel_launch(void* const* d_in, const int* in_sizes, int n_in,
                              void* d_out, int out_size)
{
    const float* q = (const float*)d_in[0];
    const float* k = (const float*)d_in[1];
    const float* v = (const float*)d_in[2];
    float* out = (float*)d_out;

    int total  = BD * HEADS * HT * XG;   // 150528 threads (2 px each)
    int blocks = total / NTHR;           // 1176
    dilate_attn_kernel<<<blocks, NTHR>>>(q, k, v, out);
}

// round 13
// speedup vs baseline: 1.2369x; 1.2369x over previous
#include <cuda_runtime.h>

// DilateAttention: B=8, C=384 (12 heads x 32), H=W=56, kernel 3x3, dilation 2, pad 2.
// q,k,v: [B, C, H, W] f32. out: [B, H, W, C] f32.
//
// R13 = R7 verbatim (2 px/thread, float2 window loads, per-window guards,
// direct full-sector stores) with the register working set cut to CC=4 AND
// 128-thread blocks, so the saving actually converts into occupancy:
// ~48 regs x 128 thr -> 10 blocks/SM feasible, 1176 blocks -> ~8 waves,
// 40 warps/SM (62.5%) vs R7's 4x256 single-wave 41.8%.
// OOB windows are skipped -> logit stays exactly 0 (unfold zero padding).

#define HD     32
#define HEADS  12
#define WD     56
#define HT     56
#define BD     8
#define HW     (WD * HT)
#define CTOT   384
#define XG     28          // x-pairs per row
#define NTHR   128
#define CC     4
#define NCH    (HD / CC)   // 8

__global__ __launch_bounds__(NTHR, 10)
void dilate_attn_kernel(const float* __restrict__ q,
                        const float* __restrict__ k,
                        const float* __restrict__ v,
                        float* __restrict__ out)
{
    const int gid  = blockIdx.x * NTHR + threadIdx.x;
    const int xg   = gid % XG;
    int r1         = gid / XG;
    const int y    = r1 % HT;
    int r2         = r1 / HT;
    const int head = r2 % HEADS;
    const int b    = r2 / HEADS;
    const int x0   = xg * 2;

    const int base = (b * CTOT + head * HD) * HW;
    const int pix  = y * WD + x0;

    const bool cL = (x0 >= 2);
    const bool cR = (x0 <= WD - 4);
    const bool yT = (y >= 2);
    const bool yB = (y <= HT - 3);

    const bool vmask[9] = {
        yT && cL, yT, yT && cR,
        cL,       true, cR,
        yB && cL, yB, yB && cR
    };
    const int voff[9] = {
        -2 * WD - 2, -2 * WD, -2 * WD + 2,
        -2,           0,       2,
         2 * WD - 2,  2 * WD,  2 * WD + 2
    };

    const float* qc = q + base + pix;
    const float* kc = k + base + pix;
    const float* vc = v + base + pix;

    const float scale = 0.17677669529663687f;  // 32^-0.5

    float a0[9], a1[9];
#pragma unroll
    for (int p = 0; p < 9; p++) { a0[p] = 0.0f; a1[p] = 0.0f; }

    // ================= K phase: logits, channel chunks of 4 =================
#pragma unroll
    for (int ch = 0; ch < NCH; ch++) {
        float2 qv[CC];
#pragma unroll
        for (int c = 0; c < CC; c++) {
            qv[c] = *(const float2*)(qc + (ch * CC + c) * HW);
            qv[c].x *= scale; qv[c].y *= scale;
        }

#pragma unroll
        for (int p = 0; p < 9; p++) {
            if (vmask[p]) {
                const float* kp = kc + ch * CC * HW + voff[p];
                float s0 = a0[p], s1 = a1[p];
#pragma unroll
                for (int c = 0; c < CC; c++) {
                    float2 kv = *(const float2*)(kp + c * HW);
                    s0 = fmaf(qv[c].x, kv.x, s0);
                    s1 = fmaf(qv[c].y, kv.y, s1);
                }
                a0[p] = s0; a1[p] = s1;
            }
        }
    }

    // ================= softmax (normalization folded into weights) =================
    {
        float m0 = -1e30f, m1 = -1e30f;
#pragma unroll
        for (int p = 0; p < 9; p++) { m0 = fmaxf(m0, a0[p]); m1 = fmaxf(m1, a1[p]); }
        float d0 = 0.0f, d1 = 0.0f;
#pragma unroll
        for (int p = 0; p < 9; p++) {
            a0[p] = __expf(a0[p] - m0); d0 += a0[p];
            a1[p] = __expf(a1[p] - m1); d1 += a1[p];
        }
        float i0 = 1.0f / d0, i1 = 1.0f / d1;
#pragma unroll
        for (int p = 0; p < 9; p++) { a0[p] *= i0; a1[p] *= i1; }
    }

    // ================= V phase: weighted sum + direct stores =================
    const int ob = ((b * HT + y) * WD + x0) * CTOT + head * HD;

#pragma unroll
    for (int ch = 0; ch < NCH; ch++) {
        float acc0[CC], acc1[CC];
#pragma unroll
        for (int c = 0; c < CC; c++) { acc0[c] = 0.0f; acc1[c] = 0.0f; }

#pragma unroll
        for (int p = 0; p < 9; p++) {
            if (vmask[p]) {
                const float w0 = a0[p], w1 = a1[p];
                const float* vp = vc + ch * CC * HW + voff[p];
#pragma unroll
                for (int c = 0; c < CC; c++) {
                    float2 vv = *(const float2*)(vp + c * HW);
                    acc0[c] = fmaf(w0, vv.x, acc0[c]);
                    acc1[c] = fmaf(w1, vv.y, acc1[c]);
                }
            }
        }

        float* o0 = out + ob + ch * CC;
        *(float4*)(o0)        = make_float4(acc0[0], acc0[1], acc0[2], acc0[3]);
        *(float4*)(o0 + CTOT) = make_float4(acc1[0], acc1[1], acc1[2], acc1[3]);
    }
}

extern "C" void kernel_launch(void* const* d_in, const int* in_sizes, int n_in,
                              void* d_out, int out_size)
{
    const float* q = (const float*)d_in[0];
    const float* k = (const float*)d_in[1];
    const float* v = (const float*)d_in[2];
    float* out = (float*)d_out;

    int total  = BD * HEADS * HT * XG;   // 150528 threads (2 px each)
    int blocks = total / NTHR;           // 1176
    dilate_attn_kernel<<<blocks, NTHR>>>(q, k, v, out);
}

// round 14
// speedup vs baseline: 1.2949x; 1.0469x over previous
#include <cuda_runtime.h>

// DilateAttention: B=8, C=384 (12 heads x 32), H=W=56, kernel 3x3, dilation 2, pad 2.
// q,k,v: [B, C, H, W] f32. out: [B, H, W, C] f32.
//
// R14 = R1's exact structure (1 px/thread, full CC=32 register-resident q,
// per-window guarded 32-deep scalar load batches -- the widest measured MLP,
// issue=25.5%) + 128-thread blocks with __launch_bounds__(128,8):
// 2352 blocks -> 8 resident blocks/SM (32 warps, 50% occ) with ~16 waves of
// turnover, vs R1's 4x256 at 39.5%. Softmax scale folded into q at load.
// OOB windows skipped -> logit exactly 0 (matches unfold zero padding).

#define HD     32
#define HEADS  12
#define WD     56
#define HT     56
#define BD     8
#define HW     (WD * HT)
#define CTOT   (HEADS * HD)
#define NTHR   128

__global__ __launch_bounds__(NTHR, 8)
void dilate_attn_kernel(const float* __restrict__ q,
                        const float* __restrict__ k,
                        const float* __restrict__ v,
                        float* __restrict__ out)
{
    int idx = blockIdx.x * NTHR + threadIdx.x;

    int x    = idx % WD;
    int y    = (idx / WD) % HT;
    int head = (idx / HW) % HEADS;
    int b    = idx / (HW * HEADS);

    const int base = (b * CTOT + head * HD) * HW;
    const int pix  = y * WD + x;

    const bool cL = (x >= 2);
    const bool cR = (x <= WD - 3);
    const bool yT = (y >= 2);
    const bool yB = (y <= HT - 3);

    const bool vmask[9] = {
        yT && cL, yT, yT && cR,
        cL,       true, cR,
        yB && cL, yB, yB && cR
    };
    const int voff[9] = {
        -2 * WD - 2, -2 * WD, -2 * WD + 2,
        -2,           0,       2,
         2 * WD - 2,  2 * WD,  2 * WD + 2
    };

    const float scale = 0.17677669529663687f;  // 32^-0.5

    // load q vector, scale folded in (coalesced across warp lanes)
    float qv[HD];
    {
        const float* qp = q + base + pix;
#pragma unroll
        for (int c = 0; c < HD; c++) qv[c] = qp[c * HW] * scale;
    }

    // ---- logits: per-window 32-deep independent load batches ----
    float attn[9];
    {
        const float* kc = k + base + pix;
#pragma unroll
        for (int p = 0; p < 9; p++) {
            float s = 0.0f;
            if (vmask[p]) {
                const float* kp = kc + voff[p];
#pragma unroll
                for (int c = 0; c < HD; c++) s = fmaf(qv[c], kp[c * HW], s);
            }
            attn[p] = s;   // OOB -> logit 0 (matches zero-padded unfold)
        }
    }

    // ---- softmax over 9 (normalization folded into weights) ----
    {
        float m = attn[0];
#pragma unroll
        for (int p = 1; p < 9; p++) m = fmaxf(m, attn[p]);
        float d = 0.0f;
#pragma unroll
        for (int p = 0; p < 9; p++) { attn[p] = __expf(attn[p] - m); d += attn[p]; }
        float inv = 1.0f / d;
#pragma unroll
        for (int p = 0; p < 9; p++) attn[p] *= inv;
    }

    // ---- weighted sum of v: same wide-batch structure ----
    float acc[HD];
#pragma unroll
    for (int c = 0; c < HD; c++) acc[c] = 0.0f;
    {
        const float* vc = v + base + pix;
#pragma unroll
        for (int p = 0; p < 9; p++) {
            if (vmask[p]) {
                const float w = attn[p];
                const float* vp = vc + voff[p];
#pragma unroll
                for (int c = 0; c < HD; c++) acc[c] = fmaf(w, vp[c * HW], acc[c]);
            }
        }
    }

    // ---- write out: out[b, y, x, head*32 + c] -- 128 contiguous bytes/thread ----
    float4* o = (float4*)(out + (size_t)((b * HT + y) * WD + x) * CTOT + head * HD);
#pragma unroll
    for (int c = 0; c < HD; c += 4)
        o[c / 4] = make_float4(acc[c], acc[c + 1], acc[c + 2], acc[c + 3]);
}

extern "C" void kernel_launch(void* const* d_in, const int* in_sizes, int n_in,
                              void* d_out, int out_size)
{
    const float* q = (const float*)d_in[0];
    const float* k = (const float*)d_in[1];
    const float* v = (const float*)d_in[2];
    float* out = (float*)d_out;

    int total  = BD * HEADS * HW;      // 301056 threads
    int blocks = total / NTHR;         // 2352
    dilate_attn_kernel<<<blocks, NTHR>>>(q, k, v, out);
}